// round 4
// baseline (speedup 1.0000x reference)
#include <cuda_runtime.h>
#include <cstdint>

#define HEADS 6
#define NTOK  64
#define DIM   96
#define NW    512
#define S     68   // shared-memory row stride (floats), 16B-aligned

typedef unsigned long long ull;

// ---------------- packed f32x2 helpers (sm_103a FFMA2 path) ----------------
__device__ __forceinline__ ull pk(float lo, float hi) {
    ull r; asm("mov.b64 %0, {%1,%2};" : "=l"(r) : "f"(lo), "f"(hi)); return r;
}
__device__ __forceinline__ void upk(ull v, float& lo, float& hi) {
    asm("mov.b64 {%0,%1}, %2;" : "=f"(lo), "=f"(hi) : "l"(v));
}
__device__ __forceinline__ ull f2fma(ull a, ull b, ull c) {
    ull d; asm("fma.rn.f32x2 %0, %1, %2, %3;" : "=l"(d) : "l"(a), "l"(b), "l"(c)); return d;
}
__device__ __forceinline__ ull f2mul(ull a, ull b) {
    ull d; asm("mul.rn.f32x2 %0, %1, %2;" : "=l"(d) : "l"(a), "l"(b)); return d;
}
__device__ __forceinline__ float hsum(ull v) {
    float lo, hi; upk(v, lo, hi); return lo + hi;
}

// Combined (rpb-gather + shift-mask) table: [w][h][n][m] fp32, ~50MB.
__device__ float cmb[NW * HEADS * NTOK * NTOK];

__global__ void prep_kernel(const float* __restrict__ rpb,
                            const int* __restrict__ ridx,
                            const float* __restrict__ mask) {
    int i = blockIdx.x * 256 + threadIdx.x;
    if (i >= NW * HEADS * NTOK * NTOK) return;
    int w   = i / (HEADS * 4096);
    int rem = i % (HEADS * 4096);
    int h   = rem / 4096;
    int nm  = rem % 4096;
    cmb[i] = rpb[ridx[nm] * HEADS + h] + mask[w * 4096 + nm];
}

// SMEM layout (floats). All matrices transposed: [channel][token], stride S=68.
//   XST [0,     6528) : x^T; dead after QKV -> aliased by ATTN [64][S]
//   WST [6528,  8064) : weight staging chunk [k=16][96]
//   QT  [8064, 14592) : Q^T (pre-scaled); per-head overwritten by o^T
//   KT  [14592,21120) : K^T
//   VT  [21120,27648) : V^T
#define XST 0
#define ATTN 0
#define WST 6528
#define QT  8064
#define KT  14592
#define VT  21120
#define SMEM_FLOATS 27648

__global__ __launch_bounds__(256, 2)
void win_attn_kernel(const float* __restrict__ x,
                     const float* __restrict__ qkv_w,
                     const float* __restrict__ qkv_b,
                     const float* __restrict__ proj_w,
                     const float* __restrict__ proj_b,
                     float* __restrict__ out)
{
    extern __shared__ float sm[];
    const int tid = threadIdx.x;
    const int b   = blockIdx.x;

    // ---- load x (64x96) and transpose into XST [c][tok] ----
    {
        const float4* xg = reinterpret_cast<const float4*>(x + (size_t)b * NTOK * DIM);
        #pragma unroll
        for (int u = 0; u < 6; ++u) {
            int e = tid + u * 256;               // 1536 float4 total
            float4 v = xg[e];
            int tok = e / 24, m = e % 24;
            float vv4[4] = {v.x, v.y, v.z, v.w};
            // rotated store order: instruction p stores component (p+m)&3
            #pragma unroll
            for (int p = 0; p < 4; ++p) {
                int cc = (p + m) & 3;
                sm[XST + (4 * m + cc) * S + tok] = vv4[cc];
            }
        }
    }
    __syncthreads();

    const int wrp = tid >> 5;       // warp id 0..7
    const int ln  = tid & 31;
    const int tb  = 8 * wrp;        // this warp's 8 contiguous tokens

    // =================== QKV GEMM (f32x2, contiguous token pairs) ===================
    #pragma unroll 1
    for (int p = 0; p < 3; ++p) {
        ull acc[4][3];
        #pragma unroll
        for (int j = 0; j < 3; ++j) {
            float bj = qkv_b[p * 96 + ln + 32 * j];
            ull pb = pk(bj, bj);
            #pragma unroll
            for (int i = 0; i < 4; ++i) acc[i][j] = pb;
        }

        #pragma unroll 1
        for (int kb = 0; kb < 96; kb += 16) {
            __syncthreads();
            for (int e = tid; e < 384; e += 256) {        // stage W chunk [16][96]
                int r = e / 24, c4 = e % 24;
                reinterpret_cast<float4*>(sm + WST)[e] =
                    *reinterpret_cast<const float4*>(
                        qkv_w + (size_t)(kb + r) * 288 + p * 96 + c4 * 4);
            }
            __syncthreads();

            #pragma unroll
            for (int kk = 0; kk < 16; ++kk) {
                const float* xrow = &sm[XST + (kb + kk) * S + tb];
                ulonglong2 xa = *reinterpret_cast<const ulonglong2*>(xrow);
                ulonglong2 xb = *reinterpret_cast<const ulonglong2*>(xrow + 4);
                ull xp0 = xa.x, xp1 = xa.y, xp2 = xb.x, xp3 = xb.y;
                #pragma unroll
                for (int j = 0; j < 3; ++j) {
                    float wv = sm[WST + kk * 96 + ln + 32 * j];
                    ull wp = pk(wv, wv);
                    acc[0][j] = f2fma(xp0, wp, acc[0][j]);
                    acc[1][j] = f2fma(xp1, wp, acc[1][j]);
                    acc[2][j] = f2fma(xp2, wp, acc[2][j]);
                    acc[3][j] = f2fma(xp3, wp, acc[3][j]);
                }
            }
        }

        const int base = (p == 0) ? QT : (p == 1) ? KT : VT;
        const ull qscale = pk(0.25f, 0.25f);              // hd^-0.5 = 16^-0.5
        #pragma unroll
        for (int j = 0; j < 3; ++j) {
            int c = ln + 32 * j;
            ull a0 = acc[0][j], a1 = acc[1][j], a2v = acc[2][j], a3 = acc[3][j];
            if (p == 0) { a0 = f2mul(a0, qscale); a1 = f2mul(a1, qscale);
                          a2v = f2mul(a2v, qscale); a3 = f2mul(a3, qscale); }
            ulonglong2 s0; s0.x = a0; s0.y = a1;
            ulonglong2 s1; s1.x = a2v; s1.y = a3;
            *reinterpret_cast<ulonglong2*>(&sm[base + c * S + tb])     = s0;
            *reinterpret_cast<ulonglong2*>(&sm[base + c * S + tb + 4]) = s1;
        }
    }
    __syncthreads();

    // =========================== attention ===========================
    const float* cw = cmb + (size_t)(b & (NW - 1)) * (HEADS * 4096);
    const int ty16 = tid >> 4;      // row group: rows 4*ty16 .. 4*ty16+3
    const int tx16 = tid & 15;
    const int m0   = tx16 * 4;      // 4 key columns (2 pairs)
    const int r0   = ty16 * 4;

    #pragma unroll 1
    for (int h = 0; h < HEADS; ++h) {
        const int cb = h * 16;

        // ---- QK^T: acc packed over col-pairs; init = cmb pair ----
        ull a2[4][2];
        #pragma unroll
        for (int i = 0; i < 4; ++i) {
            ulonglong2 cv = *reinterpret_cast<const ulonglong2*>(
                &cw[h * 4096 + (r0 + i) * 64 + m0]);
            a2[i][0] = cv.x; a2[i][1] = cv.y;
        }
        #pragma unroll
        for (int d = 0; d < 16; ++d) {
            float4 qf = *reinterpret_cast<const float4*>(&sm[QT + (cb + d) * S + r0]);
            ulonglong2 kp = *reinterpret_cast<const ulonglong2*>(&sm[KT + (cb + d) * S + m0]);
            ull qp;
            qp = pk(qf.x, qf.x); a2[0][0]=f2fma(qp,kp.x,a2[0][0]); a2[0][1]=f2fma(qp,kp.y,a2[0][1]);
            qp = pk(qf.y, qf.y); a2[1][0]=f2fma(qp,kp.x,a2[1][0]); a2[1][1]=f2fma(qp,kp.y,a2[1][1]);
            qp = pk(qf.z, qf.z); a2[2][0]=f2fma(qp,kp.x,a2[2][0]); a2[2][1]=f2fma(qp,kp.y,a2[2][1]);
            qp = pk(qf.w, qf.w); a2[3][0]=f2fma(qp,kp.x,a2[3][0]); a2[3][1]=f2fma(qp,kp.y,a2[3][1]);
        }
        #pragma unroll
        for (int i = 0; i < 4; ++i) {
            ulonglong2 sv; sv.x = a2[i][0]; sv.y = a2[i][1];
            *reinterpret_cast<ulonglong2*>(&sm[ATTN + (r0 + i) * S + m0]) = sv;
        }
        __syncthreads();

        // ---- softmax: 4 threads/row, 16 cols each, shfl width 4 ----
        {
            int row = tid >> 2;
            int c0  = (tid & 3) * 16;
            float* rp = sm + ATTN + row * S + c0;
            float4 v0 = *reinterpret_cast<float4*>(rp);
            float4 v1 = *reinterpret_cast<float4*>(rp + 4);
            float4 v2 = *reinterpret_cast<float4*>(rp + 8);
            float4 v3 = *reinterpret_cast<float4*>(rp + 12);
            float mx = fmaxf(fmaxf(fmaxf(v0.x,v0.y),fmaxf(v0.z,v0.w)),
                       fmaxf(fmaxf(fmaxf(v1.x,v1.y),fmaxf(v1.z,v1.w)),
                       fmaxf(fmaxf(fmaxf(v2.x,v2.y),fmaxf(v2.z,v2.w)),
                             fmaxf(fmaxf(v3.x,v3.y),fmaxf(v3.z,v3.w)))));
            mx = fmaxf(mx, __shfl_xor_sync(0xffffffffu, mx, 1, 4));
            mx = fmaxf(mx, __shfl_xor_sync(0xffffffffu, mx, 2, 4));
            v0.x=__expf(v0.x-mx); v0.y=__expf(v0.y-mx); v0.z=__expf(v0.z-mx); v0.w=__expf(v0.w-mx);
            v1.x=__expf(v1.x-mx); v1.y=__expf(v1.y-mx); v1.z=__expf(v1.z-mx); v1.w=__expf(v1.w-mx);
            v2.x=__expf(v2.x-mx); v2.y=__expf(v2.y-mx); v2.z=__expf(v2.z-mx); v2.w=__expf(v2.w-mx);
            v3.x=__expf(v3.x-mx); v3.y=__expf(v3.y-mx); v3.z=__expf(v3.z-mx); v3.w=__expf(v3.w-mx);
            float s = (v0.x+v0.y+v0.z+v0.w) + (v1.x+v1.y+v1.z+v1.w)
                    + (v2.x+v2.y+v2.z+v2.w) + (v3.x+v3.y+v3.z+v3.w);
            s += __shfl_xor_sync(0xffffffffu, s, 1, 4);
            s += __shfl_xor_sync(0xffffffffu, s, 2, 4);
            float inv = 1.0f / s;
            v0.x*=inv; v0.y*=inv; v0.z*=inv; v0.w*=inv;
            v1.x*=inv; v1.y*=inv; v1.z*=inv; v1.w*=inv;
            v2.x*=inv; v2.y*=inv; v2.z*=inv; v2.w*=inv;
            v3.x*=inv; v3.y*=inv; v3.z*=inv; v3.w*=inv;
            *reinterpret_cast<float4*>(rp)      = v0;
            *reinterpret_cast<float4*>(rp + 4)  = v1;
            *reinterpret_cast<float4*>(rp + 8)  = v2;
            *reinterpret_cast<float4*>(rp + 12) = v3;
        }
        __syncthreads();

        // ---- PV: f32x2, 4-wide m chunks; out channel c = cb+tx16 ----
        {
            const int c = cb + tx16;
            ull acc2[4] = {0ull, 0ull, 0ull, 0ull};
            #pragma unroll 4
            for (int m4 = 0; m4 < 16; ++m4) {
                ulonglong2 vv = *reinterpret_cast<const ulonglong2*>(
                    &sm[VT + c * S + 4 * m4]);
                #pragma unroll
                for (int i = 0; i < 4; ++i) {
                    ulonglong2 pp = *reinterpret_cast<const ulonglong2*>(
                        &sm[ATTN + (r0 + i) * S + 4 * m4]);
                    acc2[i] = f2fma(pp.x, vv.x, acc2[i]);
                    acc2[i] = f2fma(pp.y, vv.y, acc2[i]);
                }
            }
            // o^T overwrites this head's (dead) Q columns in QT
            float4 ov = make_float4(hsum(acc2[0]), hsum(acc2[1]),
                                    hsum(acc2[2]), hsum(acc2[3]));
            *reinterpret_cast<float4*>(&sm[QT + c * S + r0]) = ov;
        }
        __syncthreads();
    }

    // =================== proj GEMM (input o^T already in QT) ===================
    {
        ull acc[4][3];
        #pragma unroll
        for (int j = 0; j < 3; ++j) {
            float bj = proj_b[ln + 32 * j];
            ull pb = pk(bj, bj);
            #pragma unroll
            for (int i = 0; i < 4; ++i) acc[i][j] = pb;
        }

        #pragma unroll 1
        for (int kb = 0; kb < 96; kb += 16) {
            __syncthreads();
            for (int e = tid; e < 384; e += 256) {
                int r = e / 24, c4 = e % 24;
                reinterpret_cast<float4*>(sm + WST)[e] =
                    *reinterpret_cast<const float4*>(
                        proj_w + (size_t)(kb + r) * 96 + c4 * 4);
            }
            __syncthreads();

            #pragma unroll
            for (int kk = 0; kk < 16; ++kk) {
                const float* xrow = &sm[QT + (kb + kk) * S + tb];
                ulonglong2 xa = *reinterpret_cast<const ulonglong2*>(xrow);
                ulonglong2 xb = *reinterpret_cast<const ulonglong2*>(xrow + 4);
                ull xp0 = xa.x, xp1 = xa.y, xp2 = xb.x, xp3 = xb.y;
                #pragma unroll
                for (int j = 0; j < 3; ++j) {
                    float wv = sm[WST + kk * 96 + ln + 32 * j];
                    ull wp = pk(wv, wv);
                    acc[0][j] = f2fma(xp0, wp, acc[0][j]);
                    acc[1][j] = f2fma(xp1, wp, acc[1][j]);
                    acc[2][j] = f2fma(xp2, wp, acc[2][j]);
                    acc[3][j] = f2fma(xp3, wp, acc[3][j]);
                }
            }
        }

        float* og = out + (size_t)b * NTOK * DIM;
        #pragma unroll
        for (int i = 0; i < 4; ++i) {
            int t0 = tb + 2 * i;
            #pragma unroll
            for (int j = 0; j < 3; ++j) {
                int c = ln + 32 * j;
                float lo, hi; upk(acc[i][j], lo, hi);
                og[(size_t)t0 * 96 + c]       = lo;
                og[(size_t)(t0 + 1) * 96 + c] = hi;
            }
        }
    }
}

extern "C" void kernel_launch(void* const* d_in, const int* in_sizes, int n_in,
                              void* d_out, int out_size)
{
    const float* x      = (const float*)d_in[0];
    const float* mask   = (const float*)d_in[1];
    const float* qkv_w  = (const float*)d_in[2];
    const float* qkv_b  = (const float*)d_in[3];
    const float* proj_w = (const float*)d_in[4];
    const float* proj_b = (const float*)d_in[5];
    const float* rpb    = (const float*)d_in[6];
    const int*   ridx   = (const int*)d_in[7];
    float* out = (float*)d_out;

    const int n_windows = in_sizes[0] / (NTOK * DIM);   // 8192

    cudaFuncSetAttribute(win_attn_kernel,
                         cudaFuncAttributeMaxDynamicSharedMemorySize,
                         SMEM_FLOATS * sizeof(float));

    const int total = NW * HEADS * NTOK * NTOK;
    prep_kernel<<<(total + 255) / 256, 256>>>(rpb, ridx, mask);
    win_attn_kernel<<<n_windows, 256, SMEM_FLOATS * sizeof(float)>>>(
        x, qkv_w, qkv_b, proj_w, proj_b, out);
}

// round 6
// speedup vs baseline: 1.2618x; 1.2618x over previous
#include <cuda_runtime.h>
#include <cuda_bf16.h>
#include <cstdint>

#define HEADS 6
#define NTOK  64
#define DIM   96
#define NW    512

typedef unsigned long long ull;
typedef uint32_t u32;

// ---------------- f32x2 helpers (attention stage) ----------------
__device__ __forceinline__ ull pk(float lo, float hi) {
    ull r; asm("mov.b64 %0, {%1,%2};" : "=l"(r) : "f"(lo), "f"(hi)); return r;
}
__device__ __forceinline__ void upk(ull v, float& lo, float& hi) {
    asm("mov.b64 {%0,%1}, %2;" : "=f"(lo), "=f"(hi) : "l"(v));
}
__device__ __forceinline__ ull f2fma(ull a, ull b, ull c) {
    ull d; asm("fma.rn.f32x2 %0, %1, %2, %3;" : "=l"(d) : "l"(a), "l"(b), "l"(c)); return d;
}
__device__ __forceinline__ float hsum(ull v) {
    float lo, hi; upk(v, lo, hi); return lo + hi;
}

// ---------------- bf16 split-pack: f32 pair -> (hi pair, lo pair) ----------------
__device__ __forceinline__ void bsplit2(float f0, float f1, u32& hi, u32& lo) {
    __nv_bfloat162 h = __floats2bfloat162_rn(f0, f1);       // .x = f0 (low 16 bits)
    float r0 = f0 - __bfloat162float(h.x);
    float r1 = f1 - __bfloat162float(h.y);
    __nv_bfloat162 l = __floats2bfloat162_rn(r0, r1);
    hi = ((u32)__bfloat16_as_ushort(h.y) << 16) | __bfloat16_as_ushort(h.x);
    lo = ((u32)__bfloat16_as_ushort(l.y) << 16) | __bfloat16_as_ushort(l.x);
}

// mma.m16n8k16 row.col f32 += bf16*bf16 (HMMA; legal on plain compute_103)
__device__ __forceinline__ void mma16816(float* d, const u32* a, u32 b0, u32 b1) {
    asm volatile("mma.sync.aligned.m16n8k16.row.col.f32.bf16.bf16.f32 "
        "{%0,%1,%2,%3}, {%4,%5,%6,%7}, {%8,%9}, {%0,%1,%2,%3};"
        : "+f"(d[0]), "+f"(d[1]), "+f"(d[2]), "+f"(d[3])
        : "r"(a[0]), "r"(a[1]), "r"(a[2]), "r"(a[3]), "r"(b0), "r"(b1));
}

// Combined (rpb-gather + shift-mask) table: [w][h][n][m] fp32, ~50MB.
__device__ float cmb[NW * HEADS * NTOK * NTOK];

__global__ void prep_kernel(const float* __restrict__ rpb,
                            const int* __restrict__ ridx,
                            const float* __restrict__ mask) {
    int i = blockIdx.x * 256 + threadIdx.x;
    if (i >= NW * HEADS * NTOK * NTOK) return;
    int w = i / (HEADS * 4096), rem = i % (HEADS * 4096);
    cmb[i] = rpb[ridx[rem % 4096] * HEADS + rem / 4096] + mask[w * 4096 + rem % 4096];
}

// ---------------- SMEM layout (bytes) ----------------
// XH @ 0      : bf16 [128 tok][104 k]  (x hi; later o hi)   26624 B
// XL @ 26624  : bf16 [128][104]        (x lo; later o lo)   26624 B
//   (ATTN buffers alias XH/XL region during attention: 2 x 4352 fl)
// WH @ 53248  : bf16 [32 n][104 k]     weight chunk hi       6656 B
// WL @ 59904  : bf16 [32][104]         weight chunk lo       6656 B
// QT @ 66560  : fp32 2win x [96 ch][68 tok]  Q^T (scaled); o^T after PV
// KT @ 118784 : fp32 2win x [96][68]   K^T
// VT @ 171008 : fp32 2win x [96][68]   V^T                   end 223232
#define XH_B 0
#define XL_B 26624
#define WH_B 53248
#define WL_B 59904
#define QT_F 16640
#define KT_F 29696
#define VT_F 42752
#define WINSTR 6528            // 96*68 floats per window
#define SMEM_BYTES 223232

__global__ __launch_bounds__(512, 1)
void win_attn_kernel(const float* __restrict__ x,
                     const float* __restrict__ qkv_w,
                     const float* __restrict__ qkv_b,
                     const float* __restrict__ proj_w,
                     const float* __restrict__ proj_b,
                     float* __restrict__ out)
{
    extern __shared__ char smc[];
    float* SMF = reinterpret_cast<float*>(smc);
    const int tid  = threadIdx.x;
    const int lane = tid & 31;
    const int wid  = tid >> 5;            // 0..15
    const int m    = wid & 7;             // M-tile (16 rows each)
    const int nh   = wid >> 3;            // N-half of 32-col chunk

    // ================= phase 0: load x (2 windows = 128x96), split-pack =================
    {
        const float4* xg = reinterpret_cast<const float4*>(x + (size_t)blockIdx.x * 128 * 96);
        #pragma unroll
        for (int u = 0; u < 6; ++u) {
            int e = tid + u * 512;                 // 3072 float4
            float4 v = xg[e];
            int tok = e / 24, c4 = (e % 24) * 4;
            u32 h0, l0, h1, l1;
            bsplit2(v.x, v.y, h0, l0);
            bsplit2(v.z, v.w, h1, l1);
            uint2* ph = reinterpret_cast<uint2*>(smc + XH_B + tok * 208 + c4 * 2);
            uint2* pl = reinterpret_cast<uint2*>(smc + XL_B + tok * 208 + c4 * 2);
            *ph = make_uint2(h0, h1);
            *pl = make_uint2(l0, l1);
        }
    }

    // ================= phase 1: QKV GEMM, 9 chunks of N=32, bf16x3 =================
    #pragma unroll 1
    for (int c = 0; c < 9; ++c) {
        __syncthreads();
        // stage W chunk: cols [32c, 32c+32), k pairs packed
        #pragma unroll
        for (int u = 0; u < 3; ++u) {
            int e = tid + u * 512;                 // 1536 (n,k2) pairs
            int n = e & 31, k2 = e >> 5;           // k2 = 0..47
            float w0 = qkv_w[(size_t)(2 * k2) * 288 + c * 32 + n];
            float w1 = qkv_w[(size_t)(2 * k2 + 1) * 288 + c * 32 + n];
            u32 hi, lo; bsplit2(w0, w1, hi, lo);
            *reinterpret_cast<u32*>(smc + WH_B + n * 208 + k2 * 4) = hi;
            *reinterpret_cast<u32*>(smc + WL_B + n * 208 + k2 * 4) = lo;
        }
        __syncthreads();

        float d[2][4] = {{0.f,0.f,0.f,0.f},{0.f,0.f,0.f,0.f}};
        const int row0 = m * 16 + (lane >> 2);
        #pragma unroll
        for (int ks = 0; ks < 6; ++ks) {
            const int kb = (ks * 8 + (lane & 3)) * 4;       // byte offset of packed k-pair
            u32 ah[4], al[4];
            ah[0] = *reinterpret_cast<u32*>(smc + XH_B + row0 * 208 + kb);
            ah[1] = *reinterpret_cast<u32*>(smc + XH_B + (row0 + 8) * 208 + kb);
            ah[2] = *reinterpret_cast<u32*>(smc + XH_B + row0 * 208 + kb + 16);
            ah[3] = *reinterpret_cast<u32*>(smc + XH_B + (row0 + 8) * 208 + kb + 16);
            al[0] = *reinterpret_cast<u32*>(smc + XL_B + row0 * 208 + kb);
            al[1] = *reinterpret_cast<u32*>(smc + XL_B + (row0 + 8) * 208 + kb);
            al[2] = *reinterpret_cast<u32*>(smc + XL_B + row0 * 208 + kb + 16);
            al[3] = *reinterpret_cast<u32*>(smc + XL_B + (row0 + 8) * 208 + kb + 16);
            #pragma unroll
            for (int nt = 0; nt < 2; ++nt) {
                int n0 = nh * 16 + nt * 8 + (lane >> 2);
                u32 bh0 = *reinterpret_cast<u32*>(smc + WH_B + n0 * 208 + kb);
                u32 bh1 = *reinterpret_cast<u32*>(smc + WH_B + n0 * 208 + kb + 16);
                u32 bl0 = *reinterpret_cast<u32*>(smc + WL_B + n0 * 208 + kb);
                u32 bl1 = *reinterpret_cast<u32*>(smc + WL_B + n0 * 208 + kb + 16);
                mma16816(d[nt], ah, bh0, bh1);
                mma16816(d[nt], ah, bl0, bl1);
                mma16816(d[nt], al, bh0, bh1);
            }
        }

        // epilogue: + bias (Q also *0.25), store transposed [ch][tok]
        const int p = c / 3;
        float* dst = SMF + (p == 0 ? QT_F : p == 1 ? KT_F : VT_F);
        const int win = row0 >> 6, tk = row0 & 63;
        #pragma unroll
        for (int nt = 0; nt < 2; ++nt) {
            int g = c * 32 + nh * 16 + nt * 8 + 2 * (lane & 3);   // global col 0..287
            int ch = g % 96;
            float b0 = qkv_b[g], b1 = qkv_b[g + 1];
            float v00 = d[nt][0] + b0, v01 = d[nt][1] + b1;
            float v10 = d[nt][2] + b0, v11 = d[nt][3] + b1;
            if (p == 0) { v00 *= 0.25f; v01 *= 0.25f; v10 *= 0.25f; v11 *= 0.25f; }
            float* q0 = dst + win * WINSTR + ch * 68 + tk;
            q0[0]      = v00;   // (row , ch  )
            q0[68]     = v01;   // (row , ch+1)
            q0[8]      = v10;   // (row+8, ch )
            q0[68 + 8] = v11;
        }
    }
    __syncthreads();

    // ================= phase 2: attention (SIMT f32x2, per window) =================
    {
        const int w = tid >> 8;                 // window within CTA
        const int t = tid & 255;
        float* qtw = SMF + QT_F + w * WINSTR;
        float* ktw = SMF + KT_F + w * WINSTR;
        float* vtw = SMF + VT_F + w * WINSTR;
        float* atw = SMF + w * 4352;            // aliases dead x region
        const float* cw = cmb + (size_t)((2 * blockIdx.x + w) & (NW - 1)) * (HEADS * 4096);
        const int ty16 = t >> 4, tx16 = t & 15;
        const int m0 = tx16 * 4, r0 = ty16 * 4;

        #pragma unroll 1
        for (int h = 0; h < HEADS; ++h) {
            const int cb = h * 16;

            // ---- QK^T: col-pair accumulators init from cmb ----
            ull a2[4][2];
            #pragma unroll
            for (int i = 0; i < 4; ++i) {
                ulonglong2 cv = *reinterpret_cast<const ulonglong2*>(
                    &cw[h * 4096 + (r0 + i) * 64 + m0]);
                a2[i][0] = cv.x; a2[i][1] = cv.y;
            }
            #pragma unroll
            for (int d2 = 0; d2 < 16; ++d2) {
                float4 qf = *reinterpret_cast<const float4*>(&qtw[(cb + d2) * 68 + r0]);
                ulonglong2 kp = *reinterpret_cast<const ulonglong2*>(&ktw[(cb + d2) * 68 + m0]);
                ull qp;
                qp = pk(qf.x, qf.x); a2[0][0]=f2fma(qp,kp.x,a2[0][0]); a2[0][1]=f2fma(qp,kp.y,a2[0][1]);
                qp = pk(qf.y, qf.y); a2[1][0]=f2fma(qp,kp.x,a2[1][0]); a2[1][1]=f2fma(qp,kp.y,a2[1][1]);
                qp = pk(qf.z, qf.z); a2[2][0]=f2fma(qp,kp.x,a2[2][0]); a2[2][1]=f2fma(qp,kp.y,a2[2][1]);
                qp = pk(qf.w, qf.w); a2[3][0]=f2fma(qp,kp.x,a2[3][0]); a2[3][1]=f2fma(qp,kp.y,a2[3][1]);
            }
            #pragma unroll
            for (int i = 0; i < 4; ++i) {
                ulonglong2 sv; sv.x = a2[i][0]; sv.y = a2[i][1];
                *reinterpret_cast<ulonglong2*>(&atw[(r0 + i) * 68 + m0]) = sv;
            }
            __syncthreads();

            // ---- softmax: 4 threads/row ----
            {
                int row = t >> 2, c0 = (t & 3) * 16;
                float* rp = atw + row * 68 + c0;
                float4 v0 = *reinterpret_cast<float4*>(rp);
                float4 v1 = *reinterpret_cast<float4*>(rp + 4);
                float4 v2 = *reinterpret_cast<float4*>(rp + 8);
                float4 v3 = *reinterpret_cast<float4*>(rp + 12);
                float mx = fmaxf(fmaxf(fmaxf(v0.x,v0.y),fmaxf(v0.z,v0.w)),
                           fmaxf(fmaxf(fmaxf(v1.x,v1.y),fmaxf(v1.z,v1.w)),
                           fmaxf(fmaxf(fmaxf(v2.x,v2.y),fmaxf(v2.z,v2.w)),
                                 fmaxf(fmaxf(v3.x,v3.y),fmaxf(v3.z,v3.w)))));
                mx = fmaxf(mx, __shfl_xor_sync(0xffffffffu, mx, 1, 4));
                mx = fmaxf(mx, __shfl_xor_sync(0xffffffffu, mx, 2, 4));
                v0.x=__expf(v0.x-mx); v0.y=__expf(v0.y-mx); v0.z=__expf(v0.z-mx); v0.w=__expf(v0.w-mx);
                v1.x=__expf(v1.x-mx); v1.y=__expf(v1.y-mx); v1.z=__expf(v1.z-mx); v1.w=__expf(v1.w-mx);
                v2.x=__expf(v2.x-mx); v2.y=__expf(v2.y-mx); v2.z=__expf(v2.z-mx); v2.w=__expf(v2.w-mx);
                v3.x=__expf(v3.x-mx); v3.y=__expf(v3.y-mx); v3.z=__expf(v3.z-mx); v3.w=__expf(v3.w-mx);
                float s = (v0.x+v0.y+v0.z+v0.w) + (v1.x+v1.y+v1.z+v1.w)
                        + (v2.x+v2.y+v2.z+v2.w) + (v3.x+v3.y+v3.z+v3.w);
                s += __shfl_xor_sync(0xffffffffu, s, 1, 4);
                s += __shfl_xor_sync(0xffffffffu, s, 2, 4);
                float inv = 1.0f / s;
                v0.x*=inv; v0.y*=inv; v0.z*=inv; v0.w*=inv;
                v1.x*=inv; v1.y*=inv; v1.z*=inv; v1.w*=inv;
                v2.x*=inv; v2.y*=inv; v2.z*=inv; v2.w*=inv;
                v3.x*=inv; v3.y*=inv; v3.z*=inv; v3.w*=inv;
                *reinterpret_cast<float4*>(rp)      = v0;
                *reinterpret_cast<float4*>(rp + 4)  = v1;
                *reinterpret_cast<float4*>(rp + 8)  = v2;
                *reinterpret_cast<float4*>(rp + 12) = v3;
            }
            __syncthreads();

            // ---- PV: out channel c = cb + tx16; o^T overwrites dead Q cols ----
            {
                const int cc = cb + tx16;
                ull acc2[4] = {0ull, 0ull, 0ull, 0ull};
                #pragma unroll 4
                for (int m4 = 0; m4 < 16; ++m4) {
                    ulonglong2 vv = *reinterpret_cast<const ulonglong2*>(
                        &vtw[cc * 68 + 4 * m4]);
                    #pragma unroll
                    for (int i = 0; i < 4; ++i) {
                        ulonglong2 pp = *reinterpret_cast<const ulonglong2*>(
                            &atw[(r0 + i) * 68 + 4 * m4]);
                        acc2[i] = f2fma(pp.x, vv.x, acc2[i]);
                        acc2[i] = f2fma(pp.y, vv.y, acc2[i]);
                    }
                }
                float4 ov = make_float4(hsum(acc2[0]), hsum(acc2[1]),
                                        hsum(acc2[2]), hsum(acc2[3]));
                *reinterpret_cast<float4*>(&qtw[cc * 68 + r0]) = ov;
            }
            __syncthreads();
        }
    }

    // ================= phase 3: repack o^T -> bf16 hi/lo over dead x region =================
    __syncthreads();
    #pragma unroll
    for (int u = 0; u < 12; ++u) {
        int e = tid + u * 512;                    // 6144 packed words
        int tok = e / 48, k2 = e % 48;
        int win = tok >> 6, tkl = tok & 63;
        const float* qb = SMF + QT_F + win * WINSTR;
        float f0 = qb[(2 * k2) * 68 + tkl];
        float f1 = qb[(2 * k2 + 1) * 68 + tkl];
        u32 hi, lo; bsplit2(f0, f1, hi, lo);
        *reinterpret_cast<u32*>(smc + XH_B + tok * 208 + k2 * 4) = hi;
        *reinterpret_cast<u32*>(smc + XL_B + tok * 208 + k2 * 4) = lo;
    }

    // ================= phase 4: proj GEMM, 3 chunks of N=32, bf16x3 =================
    #pragma unroll 1
    for (int pc = 0; pc < 3; ++pc) {
        __syncthreads();
        #pragma unroll
        for (int u = 0; u < 3; ++u) {
            int e = tid + u * 512;
            int n = e & 31, k2 = e >> 5;
            float w0 = proj_w[(size_t)(2 * k2) * 96 + pc * 32 + n];
            float w1 = proj_w[(size_t)(2 * k2 + 1) * 96 + pc * 32 + n];
            u32 hi, lo; bsplit2(w0, w1, hi, lo);
            *reinterpret_cast<u32*>(smc + WH_B + n * 208 + k2 * 4) = hi;
            *reinterpret_cast<u32*>(smc + WL_B + n * 208 + k2 * 4) = lo;
        }
        __syncthreads();

        float d[2][4] = {{0.f,0.f,0.f,0.f},{0.f,0.f,0.f,0.f}};
        const int row0 = m * 16 + (lane >> 2);
        #pragma unroll
        for (int ks = 0; ks < 6; ++ks) {
            const int kb = (ks * 8 + (lane & 3)) * 4;
            u32 ah[4], al[4];
            ah[0] = *reinterpret_cast<u32*>(smc + XH_B + row0 * 208 + kb);
            ah[1] = *reinterpret_cast<u32*>(smc + XH_B + (row0 + 8) * 208 + kb);
            ah[2] = *reinterpret_cast<u32*>(smc + XH_B + row0 * 208 + kb + 16);
            ah[3] = *reinterpret_cast<u32*>(smc + XH_B + (row0 + 8) * 208 + kb + 16);
            al[0] = *reinterpret_cast<u32*>(smc + XL_B + row0 * 208 + kb);
            al[1] = *reinterpret_cast<u32*>(smc + XL_B + (row0 + 8) * 208 + kb);
            al[2] = *reinterpret_cast<u32*>(smc + XL_B + row0 * 208 + kb + 16);
            al[3] = *reinterpret_cast<u32*>(smc + XL_B + (row0 + 8) * 208 + kb + 16);
            #pragma unroll
            for (int nt = 0; nt < 2; ++nt) {
                int n0 = nh * 16 + nt * 8 + (lane >> 2);
                u32 bh0 = *reinterpret_cast<u32*>(smc + WH_B + n0 * 208 + kb);
                u32 bh1 = *reinterpret_cast<u32*>(smc + WH_B + n0 * 208 + kb + 16);
                u32 bl0 = *reinterpret_cast<u32*>(smc + WL_B + n0 * 208 + kb);
                u32 bl1 = *reinterpret_cast<u32*>(smc + WL_B + n0 * 208 + kb + 16);
                mma16816(d[nt], ah, bh0, bh1);
                mma16816(d[nt], ah, bl0, bl1);
                mma16816(d[nt], al, bh0, bh1);
            }
        }

        // epilogue: +bias, STG.64 pairs (coalesced 32B runs per row)
        float* og = out + (size_t)blockIdx.x * 128 * 96;
        #pragma unroll
        for (int nt = 0; nt < 2; ++nt) {
            int g = pc * 32 + nh * 16 + nt * 8 + 2 * (lane & 3);
            float b0 = proj_b[g], b1 = proj_b[g + 1];
            float2 v0 = make_float2(d[nt][0] + b0, d[nt][1] + b1);
            float2 v1 = make_float2(d[nt][2] + b0, d[nt][3] + b1);
            *reinterpret_cast<float2*>(og + (size_t)row0 * 96 + g)       = v0;
            *reinterpret_cast<float2*>(og + (size_t)(row0 + 8) * 96 + g) = v1;
        }
    }
}

extern "C" void kernel_launch(void* const* d_in, const int* in_sizes, int n_in,
                              void* d_out, int out_size)
{
    const float* x      = (const float*)d_in[0];
    const float* mask   = (const float*)d_in[1];
    const float* qkv_w  = (const float*)d_in[2];
    const float* qkv_b  = (const float*)d_in[3];
    const float* proj_w = (const float*)d_in[4];
    const float* proj_b = (const float*)d_in[5];
    const float* rpb    = (const float*)d_in[6];
    const int*   ridx   = (const int*)d_in[7];
    float* out = (float*)d_out;

    const int n_windows = in_sizes[0] / (NTOK * DIM);   // 8192

    cudaFuncSetAttribute(win_attn_kernel,
                         cudaFuncAttributeMaxDynamicSharedMemorySize, SMEM_BYTES);

    const int total = NW * HEADS * NTOK * NTOK;
    prep_kernel<<<(total + 255) / 256, 256>>>(rpb, ridx, mask);
    win_attn_kernel<<<n_windows / 2, 512, SMEM_BYTES>>>(
        x, qkv_w, qkv_b, proj_w, proj_b, out);
}

// round 7
// speedup vs baseline: 1.2642x; 1.0019x over previous
#include <cuda_runtime.h>
#include <cuda_bf16.h>
#include <cstdint>

#define HEADS 6
#define NTOK  64
#define DIM   96
#define NW    512

typedef unsigned long long ull;
typedef uint32_t u32;

// ---------------- f32x2 helpers (attention stage) ----------------
__device__ __forceinline__ ull pk(float lo, float hi) {
    ull r; asm("mov.b64 %0, {%1,%2};" : "=l"(r) : "f"(lo), "f"(hi)); return r;
}
__device__ __forceinline__ void upk(ull v, float& lo, float& hi) {
    asm("mov.b64 {%0,%1}, %2;" : "=f"(lo), "=f"(hi) : "l"(v));
}
__device__ __forceinline__ ull f2fma(ull a, ull b, ull c) {
    ull d; asm("fma.rn.f32x2 %0, %1, %2, %3;" : "=l"(d) : "l"(a), "l"(b), "l"(c)); return d;
}
__device__ __forceinline__ float hsum(ull v) {
    float lo, hi; upk(v, lo, hi); return lo + hi;
}

// ---------------- bf16 split-pack: f32 pair -> (hi pair, lo pair) ----------------
__device__ __forceinline__ void bsplit2(float f0, float f1, u32& hi, u32& lo) {
    __nv_bfloat162 h = __floats2bfloat162_rn(f0, f1);
    float r0 = f0 - __bfloat162float(h.x);
    float r1 = f1 - __bfloat162float(h.y);
    __nv_bfloat162 l = __floats2bfloat162_rn(r0, r1);
    hi = ((u32)__bfloat16_as_ushort(h.y) << 16) | __bfloat16_as_ushort(h.x);
    lo = ((u32)__bfloat16_as_ushort(l.y) << 16) | __bfloat16_as_ushort(l.x);
}

// mma.m16n8k16 row.col f32 += bf16*bf16
__device__ __forceinline__ void mma16816(float* d, const u32* a, u32 b0, u32 b1) {
    asm volatile("mma.sync.aligned.m16n8k16.row.col.f32.bf16.bf16.f32 "
        "{%0,%1,%2,%3}, {%4,%5,%6,%7}, {%8,%9}, {%0,%1,%2,%3};"
        : "+f"(d[0]), "+f"(d[1]), "+f"(d[2]), "+f"(d[3])
        : "r"(a[0]), "r"(a[1]), "r"(a[2]), "r"(a[3]), "r"(b0), "r"(b1));
}
// ldmatrix x4: one 16x16 bf16 fragment (A-order mats) per call
__device__ __forceinline__ void ldmx4(u32* r, u32 addr) {
    asm volatile("ldmatrix.sync.aligned.m8n8.x4.shared.b16 {%0,%1,%2,%3}, [%4];"
        : "=r"(r[0]), "=r"(r[1]), "=r"(r[2]), "=r"(r[3]) : "r"(addr));
}
__device__ __forceinline__ u32 smem_u32(const void* p) {
    u32 a; asm("{ .reg .u64 t; cvta.to.shared.u64 t, %1; cvt.u32.u64 %0, t; }"
               : "=r"(a) : "l"(p)); return a;
}

// Combined (rpb-gather + shift-mask) table: [w][h][n][m] fp32, ~50MB.
__device__ float cmb[NW * HEADS * NTOK * NTOK];

__global__ void prep_kernel(const float* __restrict__ rpb,
                            const int* __restrict__ ridx,
                            const float* __restrict__ mask) {
    int i = blockIdx.x * 256 + threadIdx.x;
    if (i >= NW * HEADS * NTOK * NTOK) return;
    int w = i / (HEADS * 4096), rem = i % (HEADS * 4096);
    cmb[i] = rpb[ridx[rem % 4096] * HEADS + rem / 4096] + mask[w * 4096 + rem % 4096];
}

// ---------------- SMEM layout (bytes) ----------------
#define XH_B 0
#define XL_B 26624
#define WH_B 53248
#define WL_B 59904
#define QT_F 16640
#define KT_F 29696
#define VT_F 42752
#define WINSTR 6528
#define SMEM_BYTES 223232

__global__ __launch_bounds__(512, 1)
void win_attn_kernel(const float* __restrict__ x,
                     const float* __restrict__ qkv_w,
                     const float* __restrict__ qkv_b,
                     const float* __restrict__ proj_w,
                     const float* __restrict__ proj_b,
                     float* __restrict__ out)
{
    extern __shared__ char smc[];
    float* SMF = reinterpret_cast<float*>(smc);
    const int tid  = threadIdx.x;
    const int lane = tid & 31;
    const int wid  = tid >> 5;
    const int m    = wid & 7;             // M-tile (16 rows)
    const int nh   = wid >> 3;            // N-half of 32-col chunk

    const u32 sb = smem_u32(smc);
    // ldmatrix lane addressing: row-in-tile + k-half
    const int lrow  = (lane & 7) + 8 * ((lane >> 3) & 1);
    const int lkoff = (lane >> 4) * 16;
    const u32 a_h = sb + XH_B + (u32)(m * 16 + lrow) * 208 + lkoff;
    const u32 a_l = sb + XL_B + (u32)(m * 16 + lrow) * 208 + lkoff;
    const u32 b_h = sb + WH_B + (u32)(nh * 16 + lrow) * 208 + lkoff;
    const u32 b_l = sb + WL_B + (u32)(nh * 16 + lrow) * 208 + lkoff;

    // ================= phase 0: load x (128x96), split-pack =================
    {
        const float4* xg = reinterpret_cast<const float4*>(x + (size_t)blockIdx.x * 128 * 96);
        #pragma unroll
        for (int u = 0; u < 6; ++u) {
            int e = tid + u * 512;
            float4 v = xg[e];
            int tok = e / 24, c4 = (e % 24) * 4;
            u32 h0, l0, h1, l1;
            bsplit2(v.x, v.y, h0, l0);
            bsplit2(v.z, v.w, h1, l1);
            *reinterpret_cast<uint2*>(smc + XH_B + tok * 208 + c4 * 2) = make_uint2(h0, h1);
            *reinterpret_cast<uint2*>(smc + XL_B + tok * 208 + c4 * 2) = make_uint2(l0, l1);
        }
    }

    // ================= phase 1: QKV GEMM, 9 chunks of N=32, bf16x3 =================
    #pragma unroll 1
    for (int c = 0; c < 9; ++c) {
        __syncthreads();
        #pragma unroll
        for (int u = 0; u < 3; ++u) {
            int e = tid + u * 512;
            int n = e & 31, k2 = e >> 5;
            float w0 = qkv_w[(size_t)(2 * k2) * 288 + c * 32 + n];
            float w1 = qkv_w[(size_t)(2 * k2 + 1) * 288 + c * 32 + n];
            u32 hi, lo; bsplit2(w0, w1, hi, lo);
            *reinterpret_cast<u32*>(smc + WH_B + n * 208 + k2 * 4) = hi;
            *reinterpret_cast<u32*>(smc + WL_B + n * 208 + k2 * 4) = lo;
        }
        __syncthreads();

        float d[2][4] = {{0.f,0.f,0.f,0.f},{0.f,0.f,0.f,0.f}};
        #pragma unroll
        for (int ks = 0; ks < 6; ++ks) {
            u32 ah[4], al[4], bh[4], bl[4];
            ldmx4(ah, a_h + ks * 32);
            ldmx4(al, a_l + ks * 32);
            ldmx4(bh, b_h + ks * 32);
            ldmx4(bl, b_l + ks * 32);
            // B x4 mats: r0=(n0-7,k0-7) r1=(n8-15,k0-7) r2=(n0-7,k8-15) r3=(n8-15,k8-15)
            mma16816(d[0], ah, bh[0], bh[2]);
            mma16816(d[0], ah, bl[0], bl[2]);
            mma16816(d[0], al, bh[0], bh[2]);
            mma16816(d[1], ah, bh[1], bh[3]);
            mma16816(d[1], ah, bl[1], bl[3]);
            mma16816(d[1], al, bh[1], bh[3]);
        }

        // epilogue: + bias (Q also *0.25), store transposed [ch][tok]
        const int p = c / 3;
        float* dst = SMF + (p == 0 ? QT_F : p == 1 ? KT_F : VT_F);
        const int row0 = m * 16 + (lane >> 2);
        const int win = row0 >> 6, tk = row0 & 63;
        #pragma unroll
        for (int nt = 0; nt < 2; ++nt) {
            int g = c * 32 + nh * 16 + nt * 8 + 2 * (lane & 3);
            int ch = g % 96;
            float b0 = qkv_b[g], b1 = qkv_b[g + 1];
            float v00 = d[nt][0] + b0, v01 = d[nt][1] + b1;
            float v10 = d[nt][2] + b0, v11 = d[nt][3] + b1;
            if (p == 0) { v00 *= 0.25f; v01 *= 0.25f; v10 *= 0.25f; v11 *= 0.25f; }
            float* q0 = dst + win * WINSTR + ch * 68 + tk;
            q0[0]      = v00;
            q0[68]     = v01;
            q0[8]      = v10;
            q0[68 + 8] = v11;
        }
    }
    __syncthreads();

    // ================= phase 2: attention (SIMT f32x2, per window) =================
    {
        const int w = tid >> 8;
        const int t = tid & 255;
        float* qtw = SMF + QT_F + w * WINSTR;
        float* ktw = SMF + KT_F + w * WINSTR;
        float* vtw = SMF + VT_F + w * WINSTR;
        float* atw = SMF + w * 4352;
        const float* cw = cmb + (size_t)((2 * blockIdx.x + w) & (NW - 1)) * (HEADS * 4096);
        const int ty16 = t >> 4, tx16 = t & 15;
        const int m0 = tx16 * 4, r0 = ty16 * 4;

        #pragma unroll 1
        for (int h = 0; h < HEADS; ++h) {
            const int cb = h * 16;

            ull a2[4][2];
            #pragma unroll
            for (int i = 0; i < 4; ++i) {
                ulonglong2 cv = *reinterpret_cast<const ulonglong2*>(
                    &cw[h * 4096 + (r0 + i) * 64 + m0]);
                a2[i][0] = cv.x; a2[i][1] = cv.y;
            }
            #pragma unroll
            for (int d2 = 0; d2 < 16; ++d2) {
                float4 qf = *reinterpret_cast<const float4*>(&qtw[(cb + d2) * 68 + r0]);
                ulonglong2 kp = *reinterpret_cast<const ulonglong2*>(&ktw[(cb + d2) * 68 + m0]);
                ull qp;
                qp = pk(qf.x, qf.x); a2[0][0]=f2fma(qp,kp.x,a2[0][0]); a2[0][1]=f2fma(qp,kp.y,a2[0][1]);
                qp = pk(qf.y, qf.y); a2[1][0]=f2fma(qp,kp.x,a2[1][0]); a2[1][1]=f2fma(qp,kp.y,a2[1][1]);
                qp = pk(qf.z, qf.z); a2[2][0]=f2fma(qp,kp.x,a2[2][0]); a2[2][1]=f2fma(qp,kp.y,a2[2][1]);
                qp = pk(qf.w, qf.w); a2[3][0]=f2fma(qp,kp.x,a2[3][0]); a2[3][1]=f2fma(qp,kp.y,a2[3][1]);
            }
            #pragma unroll
            for (int i = 0; i < 4; ++i) {
                ulonglong2 sv; sv.x = a2[i][0]; sv.y = a2[i][1];
                *reinterpret_cast<ulonglong2*>(&atw[(r0 + i) * 68 + m0]) = sv;
            }
            __syncthreads();

            {   // softmax: 4 threads/row
                int row = t >> 2, c0 = (t & 3) * 16;
                float* rp = atw + row * 68 + c0;
                float4 v0 = *reinterpret_cast<float4*>(rp);
                float4 v1 = *reinterpret_cast<float4*>(rp + 4);
                float4 v2 = *reinterpret_cast<float4*>(rp + 8);
                float4 v3 = *reinterpret_cast<float4*>(rp + 12);
                float mx = fmaxf(fmaxf(fmaxf(v0.x,v0.y),fmaxf(v0.z,v0.w)),
                           fmaxf(fmaxf(fmaxf(v1.x,v1.y),fmaxf(v1.z,v1.w)),
                           fmaxf(fmaxf(fmaxf(v2.x,v2.y),fmaxf(v2.z,v2.w)),
                                 fmaxf(fmaxf(v3.x,v3.y),fmaxf(v3.z,v3.w)))));
                mx = fmaxf(mx, __shfl_xor_sync(0xffffffffu, mx, 1, 4));
                mx = fmaxf(mx, __shfl_xor_sync(0xffffffffu, mx, 2, 4));
                v0.x=__expf(v0.x-mx); v0.y=__expf(v0.y-mx); v0.z=__expf(v0.z-mx); v0.w=__expf(v0.w-mx);
                v1.x=__expf(v1.x-mx); v1.y=__expf(v1.y-mx); v1.z=__expf(v1.z-mx); v1.w=__expf(v1.w-mx);
                v2.x=__expf(v2.x-mx); v2.y=__expf(v2.y-mx); v2.z=__expf(v2.z-mx); v2.w=__expf(v2.w-mx);
                v3.x=__expf(v3.x-mx); v3.y=__expf(v3.y-mx); v3.z=__expf(v3.z-mx); v3.w=__expf(v3.w-mx);
                float s = (v0.x+v0.y+v0.z+v0.w) + (v1.x+v1.y+v1.z+v1.w)
                        + (v2.x+v2.y+v2.z+v2.w) + (v3.x+v3.y+v3.z+v3.w);
                s += __shfl_xor_sync(0xffffffffu, s, 1, 4);
                s += __shfl_xor_sync(0xffffffffu, s, 2, 4);
                float inv = 1.0f / s;
                v0.x*=inv; v0.y*=inv; v0.z*=inv; v0.w*=inv;
                v1.x*=inv; v1.y*=inv; v1.z*=inv; v1.w*=inv;
                v2.x*=inv; v2.y*=inv; v2.z*=inv; v2.w*=inv;
                v3.x*=inv; v3.y*=inv; v3.z*=inv; v3.w*=inv;
                *reinterpret_cast<float4*>(rp)      = v0;
                *reinterpret_cast<float4*>(rp + 4)  = v1;
                *reinterpret_cast<float4*>(rp + 8)  = v2;
                *reinterpret_cast<float4*>(rp + 12) = v3;
            }
            __syncthreads();

            {   // PV
                const int cc = cb + tx16;
                ull acc2[4] = {0ull, 0ull, 0ull, 0ull};
                #pragma unroll 4
                for (int m4 = 0; m4 < 16; ++m4) {
                    ulonglong2 vv = *reinterpret_cast<const ulonglong2*>(
                        &vtw[cc * 68 + 4 * m4]);
                    #pragma unroll
                    for (int i = 0; i < 4; ++i) {
                        ulonglong2 pp = *reinterpret_cast<const ulonglong2*>(
                            &atw[(r0 + i) * 68 + 4 * m4]);
                        acc2[i] = f2fma(pp.x, vv.x, acc2[i]);
                        acc2[i] = f2fma(pp.y, vv.y, acc2[i]);
                    }
                }
                float4 ov = make_float4(hsum(acc2[0]), hsum(acc2[1]),
                                        hsum(acc2[2]), hsum(acc2[3]));
                *reinterpret_cast<float4*>(&qtw[cc * 68 + r0]) = ov;
            }
            __syncthreads();
        }
    }

    // ================= phase 3: repack o^T -> bf16 hi/lo over dead x region =================
    __syncthreads();
    #pragma unroll
    for (int u = 0; u < 12; ++u) {
        int e = tid + u * 512;
        int tok = e / 48, k2 = e % 48;
        int win = tok >> 6, tkl = tok & 63;
        const float* qb = SMF + QT_F + win * WINSTR;
        float f0 = qb[(2 * k2) * 68 + tkl];
        float f1 = qb[(2 * k2 + 1) * 68 + tkl];
        u32 hi, lo; bsplit2(f0, f1, hi, lo);
        *reinterpret_cast<u32*>(smc + XH_B + tok * 208 + k2 * 4) = hi;
        *reinterpret_cast<u32*>(smc + XL_B + tok * 208 + k2 * 4) = lo;
    }

    // ================= phase 4: proj GEMM, 3 chunks of N=32, bf16x3 =================
    #pragma unroll 1
    for (int pc = 0; pc < 3; ++pc) {
        __syncthreads();
        #pragma unroll
        for (int u = 0; u < 3; ++u) {
            int e = tid + u * 512;
            int n = e & 31, k2 = e >> 5;
            float w0 = proj_w[(size_t)(2 * k2) * 96 + pc * 32 + n];
            float w1 = proj_w[(size_t)(2 * k2 + 1) * 96 + pc * 32 + n];
            u32 hi, lo; bsplit2(w0, w1, hi, lo);
            *reinterpret_cast<u32*>(smc + WH_B + n * 208 + k2 * 4) = hi;
            *reinterpret_cast<u32*>(smc + WL_B + n * 208 + k2 * 4) = lo;
        }
        __syncthreads();

        float d[2][4] = {{0.f,0.f,0.f,0.f},{0.f,0.f,0.f,0.f}};
        #pragma unroll
        for (int ks = 0; ks < 6; ++ks) {
            u32 ah[4], al[4], bh[4], bl[4];
            ldmx4(ah, a_h + ks * 32);
            ldmx4(al, a_l + ks * 32);
            ldmx4(bh, b_h + ks * 32);
            ldmx4(bl, b_l + ks * 32);
            mma16816(d[0], ah, bh[0], bh[2]);
            mma16816(d[0], ah, bl[0], bl[2]);
            mma16816(d[0], al, bh[0], bh[2]);
            mma16816(d[1], ah, bh[1], bh[3]);
            mma16816(d[1], ah, bl[1], bl[3]);
            mma16816(d[1], al, bh[1], bh[3]);
        }

        float* og = out + (size_t)blockIdx.x * 128 * 96;
        const int row0 = m * 16 + (lane >> 2);
        #pragma unroll
        for (int nt = 0; nt < 2; ++nt) {
            int g = pc * 32 + nh * 16 + nt * 8 + 2 * (lane & 3);
            float b0 = proj_b[g], b1 = proj_b[g + 1];
            float2 v0 = make_float2(d[nt][0] + b0, d[nt][1] + b1);
            float2 v1 = make_float2(d[nt][2] + b0, d[nt][3] + b1);
            *reinterpret_cast<float2*>(og + (size_t)row0 * 96 + g)       = v0;
            *reinterpret_cast<float2*>(og + (size_t)(row0 + 8) * 96 + g) = v1;
        }
    }
}

extern "C" void kernel_launch(void* const* d_in, const int* in_sizes, int n_in,
                              void* d_out, int out_size)
{
    const float* x      = (const float*)d_in[0];
    const float* mask   = (const float*)d_in[1];
    const float* qkv_w  = (const float*)d_in[2];
    const float* qkv_b  = (const float*)d_in[3];
    const float* proj_w = (const float*)d_in[4];
    const float* proj_b = (const float*)d_in[5];
    const float* rpb    = (const float*)d_in[6];
    const int*   ridx   = (const int*)d_in[7];
    float* out = (float*)d_out;

    const int n_windows = in_sizes[0] / (NTOK * DIM);   // 8192

    cudaFuncSetAttribute(win_attn_kernel,
                         cudaFuncAttributeMaxDynamicSharedMemorySize, SMEM_BYTES);

    const int total = NW * HEADS * NTOK * NTOK;
    prep_kernel<<<(total + 255) / 256, 256>>>(rpb, ridx, mask);
    win_attn_kernel<<<n_windows / 2, 512, SMEM_BYTES>>>(
        x, qkv_w, qkv_b, proj_w, proj_b, out);
}

// round 9
// speedup vs baseline: 1.8671x; 1.4769x over previous
#include <cuda_runtime.h>
#include <cuda_bf16.h>
#include <cstdint>

#define HEADS 6
#define NTOK  64
#define DIM   96
#define NW    512

typedef uint32_t u32;

// ---------------- bf16 split-pack: f32 pair -> (hi pair, lo pair) ----------------
__device__ __forceinline__ void bsplit2(float f0, float f1, u32& hi, u32& lo) {
    __nv_bfloat162 h = __floats2bfloat162_rn(f0, f1);
    float r0 = f0 - __bfloat162float(h.x);
    float r1 = f1 - __bfloat162float(h.y);
    __nv_bfloat162 l = __floats2bfloat162_rn(r0, r1);
    hi = ((u32)__bfloat16_as_ushort(h.y) << 16) | __bfloat16_as_ushort(h.x);
    lo = ((u32)__bfloat16_as_ushort(l.y) << 16) | __bfloat16_as_ushort(l.x);
}

// mma.m16n8k16 row.col f32 += bf16*bf16
__device__ __forceinline__ void mma16816(float* d, const u32* a, u32 b0, u32 b1) {
    asm volatile("mma.sync.aligned.m16n8k16.row.col.f32.bf16.bf16.f32 "
        "{%0,%1,%2,%3}, {%4,%5,%6,%7}, {%8,%9}, {%0,%1,%2,%3};"
        : "+f"(d[0]), "+f"(d[1]), "+f"(d[2]), "+f"(d[3])
        : "r"(a[0]), "r"(a[1]), "r"(a[2]), "r"(a[3]), "r"(b0), "r"(b1));
}
__device__ __forceinline__ void ldmx4(u32* r, u32 addr) {
    asm volatile("ldmatrix.sync.aligned.m8n8.x4.shared.b16 {%0,%1,%2,%3}, [%4];"
        : "=r"(r[0]), "=r"(r[1]), "=r"(r[2]), "=r"(r[3]) : "r"(addr));
}
__device__ __forceinline__ void ldmx4t(u32* r, u32 addr) {
    asm volatile("ldmatrix.sync.aligned.m8n8.x4.trans.shared.b16 {%0,%1,%2,%3}, [%4];"
        : "=r"(r[0]), "=r"(r[1]), "=r"(r[2]), "=r"(r[3]) : "r"(addr));
}
__device__ __forceinline__ u32 smem_u32(const void* p) {
    u32 a; asm("{ .reg .u64 t; cvta.to.shared.u64 t, %1; cvt.u32.u64 %0, t; }"
               : "=r"(a) : "l"(p)); return a;
}

// Combined (rpb-gather + shift-mask) table: [w][h][n][m] fp32, ~50MB.
__device__ float cmb[NW * HEADS * NTOK * NTOK];

__global__ void prep_kernel(const float* __restrict__ rpb,
                            const int* __restrict__ ridx,
                            const float* __restrict__ mask) {
    int i = blockIdx.x * 256 + threadIdx.x;
    if (i >= NW * HEADS * NTOK * NTOK) return;
    int w = i / (HEADS * 4096), rem = i % (HEADS * 4096);
    cmb[i] = rpb[ridx[rem % 4096] * HEADS + rem / 4096] + mask[w * 4096 + rem % 4096];
}

// ---------------- SMEM layout (bytes); all bf16 tiles have 208B row stride ----
// XH/XL: x hi/lo [128 gtok][48 u32]; reused as OH/OL (attention output) later
// WH/WL: weight chunk [32 n][48 u32]   (NOTE: WL-WH = 6656, NOT HLOFF!)
// QH/QL, KH/KL, VH/VL: per CTA 2 windows x [64 tok][48 u32] (96 ch pairs)
#define XH_B 0
#define XL_B 26624
#define WH_B 53248
#define WL_B 59904
#define QH_B 66560
#define KH_B 119808
#define VH_B 173056
#define HLOFF 26624           // (lo buffer) - (hi buffer) for X/Q/K/V regions
#define WINB 13312            // 64 * 208
#define SMEM_BYTES 226304

__global__ __launch_bounds__(512, 1)
void win_attn_kernel(const float* __restrict__ x,
                     const float* __restrict__ qkv_w,
                     const float* __restrict__ qkv_b,
                     const float* __restrict__ proj_w,
                     const float* __restrict__ proj_b,
                     float* __restrict__ out)
{
    extern __shared__ char smc[];
    const int tid  = threadIdx.x;
    const int lane = tid & 31;
    const int wid  = tid >> 5;
    const int m    = wid & 7;             // GEMM M-tile (16 rows)
    const int nh   = wid >> 3;            // GEMM N-half of 32-col chunk

    const u32 sb = smem_u32(smc);
    const int lrow  = (lane & 7) + 8 * ((lane >> 3) & 1);
    const int lkoff = (lane >> 4) * 16;
    const u32 a_h = sb + XH_B + (u32)(m * 16 + lrow) * 208 + lkoff;
    const u32 a_l = sb + XL_B + (u32)(m * 16 + lrow) * 208 + lkoff;
    const u32 b_h = sb + WH_B + (u32)(nh * 16 + lrow) * 208 + lkoff;
    const u32 b_l = sb + WL_B + (u32)(nh * 16 + lrow) * 208 + lkoff;   // R8 bug fixed

    // ================= phase 0: load x (128x96), split-pack =================
    {
        const float4* xg = reinterpret_cast<const float4*>(x + (size_t)blockIdx.x * 128 * 96);
        #pragma unroll
        for (int u = 0; u < 6; ++u) {
            int e = tid + u * 512;
            float4 v = xg[e];
            int tok = e / 24, c4 = (e % 24) * 4;
            u32 h0, l0, h1, l1;
            bsplit2(v.x, v.y, h0, l0);
            bsplit2(v.z, v.w, h1, l1);
            *reinterpret_cast<uint2*>(smc + XH_B + tok * 208 + c4 * 2) = make_uint2(h0, h1);
            *reinterpret_cast<uint2*>(smc + XL_B + tok * 208 + c4 * 2) = make_uint2(l0, l1);
        }
    }

    // ================= phase 1: QKV GEMM, 9 chunks of N=32, bf16x3 =================
    #pragma unroll 1
    for (int c = 0; c < 9; ++c) {
        __syncthreads();
        #pragma unroll
        for (int u = 0; u < 3; ++u) {
            int e = tid + u * 512;
            int n = e & 31, k2 = e >> 5;
            float w0 = qkv_w[(size_t)(2 * k2) * 288 + c * 32 + n];
            float w1 = qkv_w[(size_t)(2 * k2 + 1) * 288 + c * 32 + n];
            u32 hi, lo; bsplit2(w0, w1, hi, lo);
            *reinterpret_cast<u32*>(smc + WH_B + n * 208 + k2 * 4) = hi;
            *reinterpret_cast<u32*>(smc + WL_B + n * 208 + k2 * 4) = lo;
        }
        __syncthreads();

        float d[2][4] = {{0.f,0.f,0.f,0.f},{0.f,0.f,0.f,0.f}};
        #pragma unroll
        for (int ks = 0; ks < 6; ++ks) {
            u32 ah[4], al[4], bh[4], bl[4];
            ldmx4(ah, a_h + ks * 32);
            ldmx4(al, a_l + ks * 32);
            ldmx4(bh, b_h + ks * 32);
            ldmx4(bl, b_l + ks * 32);
            mma16816(d[0], ah, bh[0], bh[2]);
            mma16816(d[0], ah, bl[0], bl[2]);
            mma16816(d[0], al, bh[0], bh[2]);
            mma16816(d[1], ah, bh[1], bh[3]);
            mma16816(d[1], ah, bl[1], bl[3]);
            mma16816(d[1], al, bh[1], bh[3]);
        }

        // epilogue: +bias (Q also *0.25), split-pack into QH/KH/VH [tok][ch pairs]
        const int p = c / 3;
        const int base_h = (p == 0) ? QH_B : (p == 1) ? KH_B : VH_B;
        const int row0 = m * 16 + (lane >> 2);
        const int win = row0 >> 6, tk = row0 & 63;
        char* outh = smc + base_h + win * WINB + tk * 208;
        char* outl = outh + HLOFF;
        #pragma unroll
        for (int nt = 0; nt < 2; ++nt) {
            int g = c * 32 + nh * 16 + nt * 8 + 2 * (lane & 3);
            int ch = g % 96;
            float bb0 = qkv_b[g], bb1 = qkv_b[g + 1];
            float v00 = d[nt][0] + bb0, v01 = d[nt][1] + bb1;
            float v10 = d[nt][2] + bb0, v11 = d[nt][3] + bb1;
            if (p == 0) { v00 *= 0.25f; v01 *= 0.25f; v10 *= 0.25f; v11 *= 0.25f; }
            u32 hh, ll;
            bsplit2(v00, v01, hh, ll);
            *reinterpret_cast<u32*>(outh + (ch >> 1) * 4) = hh;
            *reinterpret_cast<u32*>(outl + (ch >> 1) * 4) = ll;
            bsplit2(v10, v11, hh, ll);
            *reinterpret_cast<u32*>(outh + 8 * 208 + (ch >> 1) * 4) = hh;
            *reinterpret_cast<u32*>(outl + 8 * 208 + (ch >> 1) * 4) = ll;
        }
    }
    __syncthreads();

    // ================= phase 2: attention, all-MMA, softmax in registers ==========
    {
        const int win  = wid >> 3;            // window 0/1
        const int hsub = (wid >> 2) & 1;      // head parity
        const int mt   = wid & 3;             // 16-row q tile
        const int r    = mt * 16 + (lane >> 2);
        const float* cw = cmb + (size_t)((2 * blockIdx.x + win) & (NW - 1)) * (HEADS * 4096);
        const u32 qbase = sb + QH_B + win * WINB + (u32)(mt * 16 + lrow) * 208 + lkoff;
        const u32 kbase = sb + KH_B + win * WINB + (u32)lrow * 208 + lkoff;
        const u32 vbase = sb + VH_B + win * WINB + (u32)lrow * 208 + lkoff;
        char* ooh = smc + XH_B + (win * 64 + mt * 16 + (lane >> 2)) * 208;
        char* ool = ooh + HLOFF;

        #pragma unroll 1
        for (int hi2 = 0; hi2 < 3; ++hi2) {
            const int h = 2 * hi2 + hsub;
            const u32 chb = h * 32;

            // ---- QK^T (bf16x3), acc init from cmb ----
            u32 qh4[4], ql4[4];
            ldmx4(qh4, qbase + chb);
            ldmx4(ql4, qbase + HLOFF + chb);

            float d[8][4];
            const float* cm = cw + h * 4096 + 2 * (lane & 3);
            #pragma unroll
            for (int j = 0; j < 8; ++j) {
                float2 c0 = *reinterpret_cast<const float2*>(&cm[r * 64 + 8 * j]);
                float2 c1 = *reinterpret_cast<const float2*>(&cm[(r + 8) * 64 + 8 * j]);
                d[j][0] = c0.x; d[j][1] = c0.y; d[j][2] = c1.x; d[j][3] = c1.y;
            }
            #pragma unroll
            for (int t = 0; t < 4; ++t) {
                u32 kh4[4], kl4[4];
                ldmx4(kh4, kbase + t * (16 * 208) + chb);
                ldmx4(kl4, kbase + HLOFF + t * (16 * 208) + chb);
                mma16816(d[2 * t],     qh4, kh4[0], kh4[2]);
                mma16816(d[2 * t],     qh4, kl4[0], kl4[2]);
                mma16816(d[2 * t],     ql4, kh4[0], kh4[2]);
                mma16816(d[2 * t + 1], qh4, kh4[1], kh4[3]);
                mma16816(d[2 * t + 1], qh4, kl4[1], kl4[3]);
                mma16816(d[2 * t + 1], ql4, kh4[1], kh4[3]);
            }

            // ---- softmax in registers (rows r and r+8; quad shares a row) ----
            float mx0 = -1e30f, mx1 = -1e30f;
            #pragma unroll
            for (int j = 0; j < 8; ++j) {
                mx0 = fmaxf(mx0, fmaxf(d[j][0], d[j][1]));
                mx1 = fmaxf(mx1, fmaxf(d[j][2], d[j][3]));
            }
            mx0 = fmaxf(mx0, __shfl_xor_sync(0xffffffffu, mx0, 1, 4));
            mx0 = fmaxf(mx0, __shfl_xor_sync(0xffffffffu, mx0, 2, 4));
            mx1 = fmaxf(mx1, __shfl_xor_sync(0xffffffffu, mx1, 1, 4));
            mx1 = fmaxf(mx1, __shfl_xor_sync(0xffffffffu, mx1, 2, 4));
            float s0 = 0.f, s1 = 0.f;
            #pragma unroll
            for (int j = 0; j < 8; ++j) {
                d[j][0] = __expf(d[j][0] - mx0); d[j][1] = __expf(d[j][1] - mx0);
                d[j][2] = __expf(d[j][2] - mx1); d[j][3] = __expf(d[j][3] - mx1);
                s0 += d[j][0] + d[j][1];
                s1 += d[j][2] + d[j][3];
            }
            s0 += __shfl_xor_sync(0xffffffffu, s0, 1, 4);
            s0 += __shfl_xor_sync(0xffffffffu, s0, 2, 4);
            s1 += __shfl_xor_sync(0xffffffffu, s1, 1, 4);
            s1 += __shfl_xor_sync(0xffffffffu, s1, 2, 4);
            const float inv0 = 1.0f / s0, inv1 = 1.0f / s1;

            // ---- PV (bf16x3): P fragments built in registers; V via ldmatrix.trans ----
            float o0[4] = {0.f,0.f,0.f,0.f}, o1[4] = {0.f,0.f,0.f,0.f};
            #pragma unroll
            for (int ks = 0; ks < 4; ++ks) {
                u32 pah[4], pal[4];
                bsplit2(d[2*ks][0]   * inv0, d[2*ks][1]   * inv0, pah[0], pal[0]);
                bsplit2(d[2*ks][2]   * inv1, d[2*ks][3]   * inv1, pah[1], pal[1]);
                bsplit2(d[2*ks+1][0] * inv0, d[2*ks+1][1] * inv0, pah[2], pal[2]);
                bsplit2(d[2*ks+1][2] * inv1, d[2*ks+1][3] * inv1, pah[3], pal[3]);
                u32 vh4[4], vl4[4];
                ldmx4t(vh4, vbase + ks * (16 * 208) + chb);
                ldmx4t(vl4, vbase + HLOFF + ks * (16 * 208) + chb);
                mma16816(o0, pah, vh4[0], vh4[1]);
                mma16816(o0, pah, vl4[0], vl4[1]);
                mma16816(o0, pal, vh4[0], vh4[1]);
                mma16816(o1, pah, vh4[2], vh4[3]);
                mma16816(o1, pah, vl4[2], vl4[3]);
                mma16816(o1, pal, vh4[2], vh4[3]);
            }

            // ---- o epilogue: split-pack into OH/OL (dead x region) ----
            {
                int ch0 = h * 16 + 2 * (lane & 3);
                u32 hh, ll;
                bsplit2(o0[0], o0[1], hh, ll);
                *reinterpret_cast<u32*>(ooh + (ch0 >> 1) * 4) = hh;
                *reinterpret_cast<u32*>(ool + (ch0 >> 1) * 4) = ll;
                bsplit2(o0[2], o0[3], hh, ll);
                *reinterpret_cast<u32*>(ooh + 8 * 208 + (ch0 >> 1) * 4) = hh;
                *reinterpret_cast<u32*>(ool + 8 * 208 + (ch0 >> 1) * 4) = ll;
                int ch1 = ch0 + 8;
                bsplit2(o1[0], o1[1], hh, ll);
                *reinterpret_cast<u32*>(ooh + (ch1 >> 1) * 4) = hh;
                *reinterpret_cast<u32*>(ool + (ch1 >> 1) * 4) = ll;
                bsplit2(o1[2], o1[3], hh, ll);
                *reinterpret_cast<u32*>(ooh + 8 * 208 + (ch1 >> 1) * 4) = hh;
                *reinterpret_cast<u32*>(ool + 8 * 208 + (ch1 >> 1) * 4) = ll;
            }
        }
    }
    __syncthreads();

    // ================= phase 3: proj GEMM (reads OH/OL in x region), N=32 x3 =======
    #pragma unroll 1
    for (int pc = 0; pc < 3; ++pc) {
        if (pc) __syncthreads();
        #pragma unroll
        for (int u = 0; u < 3; ++u) {
            int e = tid + u * 512;
            int n = e & 31, k2 = e >> 5;
            float w0 = proj_w[(size_t)(2 * k2) * 96 + pc * 32 + n];
            float w1 = proj_w[(size_t)(2 * k2 + 1) * 96 + pc * 32 + n];
            u32 hi, lo; bsplit2(w0, w1, hi, lo);
            *reinterpret_cast<u32*>(smc + WH_B + n * 208 + k2 * 4) = hi;
            *reinterpret_cast<u32*>(smc + WL_B + n * 208 + k2 * 4) = lo;
        }
        __syncthreads();

        float d[2][4] = {{0.f,0.f,0.f,0.f},{0.f,0.f,0.f,0.f}};
        #pragma unroll
        for (int ks = 0; ks < 6; ++ks) {
            u32 ah[4], al[4], bh[4], bl[4];
            ldmx4(ah, a_h + ks * 32);
            ldmx4(al, a_l + ks * 32);
            ldmx4(bh, b_h + ks * 32);
            ldmx4(bl, b_l + ks * 32);
            mma16816(d[0], ah, bh[0], bh[2]);
            mma16816(d[0], ah, bl[0], bl[2]);
            mma16816(d[0], al, bh[0], bh[2]);
            mma16816(d[1], ah, bh[1], bh[3]);
            mma16816(d[1], ah, bl[1], bl[3]);
            mma16816(d[1], al, bh[1], bh[3]);
        }

        float* og = out + (size_t)blockIdx.x * 128 * 96;
        const int row0 = m * 16 + (lane >> 2);
        #pragma unroll
        for (int nt = 0; nt < 2; ++nt) {
            int g = pc * 32 + nh * 16 + nt * 8 + 2 * (lane & 3);
            float b0 = proj_b[g], b1 = proj_b[g + 1];
            float2 v0 = make_float2(d[nt][0] + b0, d[nt][1] + b1);
            float2 v1 = make_float2(d[nt][2] + b0, d[nt][3] + b1);
            *reinterpret_cast<float2*>(og + (size_t)row0 * 96 + g)       = v0;
            *reinterpret_cast<float2*>(og + (size_t)(row0 + 8) * 96 + g) = v1;
        }
    }
}

extern "C" void kernel_launch(void* const* d_in, const int* in_sizes, int n_in,
                              void* d_out, int out_size)
{
    const float* x      = (const float*)d_in[0];
    const float* mask   = (const float*)d_in[1];
    const float* qkv_w  = (const float*)d_in[2];
    const float* qkv_b  = (const float*)d_in[3];
    const float* proj_w = (const float*)d_in[4];
    const float* proj_b = (const float*)d_in[5];
    const float* rpb    = (const float*)d_in[6];
    const int*   ridx   = (const int*)d_in[7];
    float* out = (float*)d_out;

    const int n_windows = in_sizes[0] / (NTOK * DIM);   // 8192

    cudaFuncSetAttribute(win_attn_kernel,
                         cudaFuncAttributeMaxDynamicSharedMemorySize, SMEM_BYTES);

    const int total = NW * HEADS * NTOK * NTOK;
    prep_kernel<<<(total + 255) / 256, 256>>>(rpb, ridx, mask);
    win_attn_kernel<<<n_windows / 2, 512, SMEM_BYTES>>>(
        x, qkv_w, qkv_b, proj_w, proj_b, out);
}

// round 10
// speedup vs baseline: 1.9532x; 1.0461x over previous
#include <cuda_runtime.h>
#include <cuda_bf16.h>
#include <cstdint>

#define HEADS 6
#define NTOK  64
#define DIM   96
#define NW    512

typedef uint32_t u32;

// ---------------- bf16 split-pack: f32 pair -> (hi pair, lo pair) ----------------
__device__ __forceinline__ void bsplit2(float f0, float f1, u32& hi, u32& lo) {
    __nv_bfloat162 h = __floats2bfloat162_rn(f0, f1);
    float r0 = f0 - __bfloat162float(h.x);
    float r1 = f1 - __bfloat162float(h.y);
    __nv_bfloat162 l = __floats2bfloat162_rn(r0, r1);
    hi = ((u32)__bfloat16_as_ushort(h.y) << 16) | __bfloat16_as_ushort(h.x);
    lo = ((u32)__bfloat16_as_ushort(l.y) << 16) | __bfloat16_as_ushort(l.x);
}

// mma.m16n8k16 row.col f32 += bf16*bf16
__device__ __forceinline__ void mma16816(float* d, const u32* a, u32 b0, u32 b1) {
    asm volatile("mma.sync.aligned.m16n8k16.row.col.f32.bf16.bf16.f32 "
        "{%0,%1,%2,%3}, {%4,%5,%6,%7}, {%8,%9}, {%0,%1,%2,%3};"
        : "+f"(d[0]), "+f"(d[1]), "+f"(d[2]), "+f"(d[3])
        : "r"(a[0]), "r"(a[1]), "r"(a[2]), "r"(a[3]), "r"(b0), "r"(b1));
}
__device__ __forceinline__ void ldmx4(u32* r, u32 addr) {
    asm volatile("ldmatrix.sync.aligned.m8n8.x4.shared.b16 {%0,%1,%2,%3}, [%4];"
        : "=r"(r[0]), "=r"(r[1]), "=r"(r[2]), "=r"(r[3]) : "r"(addr));
}
__device__ __forceinline__ void ldmx4t(u32* r, u32 addr) {
    asm volatile("ldmatrix.sync.aligned.m8n8.x4.trans.shared.b16 {%0,%1,%2,%3}, [%4];"
        : "=r"(r[0]), "=r"(r[1]), "=r"(r[2]), "=r"(r[3]) : "r"(addr));
}
__device__ __forceinline__ u32 smem_u32(const void* p) {
    u32 a; asm("{ .reg .u64 t; cvta.to.shared.u64 t, %1; cvt.u32.u64 %0, t; }"
               : "=r"(a) : "l"(p)); return a;
}

// Combined (rpb-gather + shift-mask) table: [w][h][n][m] fp32, ~50MB.
__device__ float cmb[NW * HEADS * NTOK * NTOK];

__global__ void prep_kernel(const float* __restrict__ rpb,
                            const int* __restrict__ ridx,
                            const float* __restrict__ mask) {
    int i = blockIdx.x * 256 + threadIdx.x;
    if (i >= NW * HEADS * NTOK * NTOK) return;
    int w = i / (HEADS * 4096), rem = i % (HEADS * 4096);
    cmb[i] = rpb[ridx[rem % 4096] * HEADS + rem / 4096] + mask[w * 4096 + rem % 4096];
}

// ---------------- SMEM layout (bytes); all bf16 tiles have 208B row stride ----
#define XH_B 0
#define XL_B 26624
#define WH_B 53248
#define WL_B 59904
#define QH_B 66560
#define KH_B 119808
#define VH_B 173056
#define HLOFF 26624           // (lo - hi) for X/Q/K/V regions (NOT W: WL-WH=6656)
#define WINB 13312            // 64 * 208
#define SMEM_BYTES 226304

__global__ __launch_bounds__(512, 1)
void win_attn_kernel(const float* __restrict__ x,
                     const float* __restrict__ qkv_w,
                     const float* __restrict__ qkv_b,
                     const float* __restrict__ proj_w,
                     const float* __restrict__ proj_b,
                     float* __restrict__ out)
{
    extern __shared__ char smc[];
    const int tid  = threadIdx.x;
    const int lane = tid & 31;
    const int wid  = tid >> 5;
    const int m    = wid & 7;             // GEMM M-tile (16 rows)
    const int nh   = wid >> 3;            // GEMM N-half of 32-col chunk

    const u32 sb = smem_u32(smc);
    const int lrow  = (lane & 7) + 8 * ((lane >> 3) & 1);
    const int lkoff = (lane >> 4) * 16;
    const u32 a_h = sb + XH_B + (u32)(m * 16 + lrow) * 208 + lkoff;
    const u32 a_l = sb + XL_B + (u32)(m * 16 + lrow) * 208 + lkoff;
    const u32 b_h = sb + WH_B + (u32)(nh * 16 + lrow) * 208 + lkoff;
    const u32 b_l = sb + WL_B + (u32)(nh * 16 + lrow) * 208 + lkoff;

    // staging-thread indices (same for every chunk)
    const int se_n[3]  = { tid & 31, (tid + 512) & 31, (tid + 1024) & 31 };
    const int se_k2[3] = { tid >> 5, (tid + 512) >> 5, (tid + 1024) >> 5 };

    // ---- prefetch W chunk 0 ----
    float wv0[3], wv1[3];
    #pragma unroll
    for (int u = 0; u < 3; ++u) {
        wv0[u] = qkv_w[(size_t)(2 * se_k2[u]) * 288 + se_n[u]];
        wv1[u] = qkv_w[(size_t)(2 * se_k2[u] + 1) * 288 + se_n[u]];
    }

    // ================= phase 0: load x (128x96), split-pack =================
    {
        const float4* xg = reinterpret_cast<const float4*>(x + (size_t)blockIdx.x * 128 * 96);
        #pragma unroll
        for (int u = 0; u < 6; ++u) {
            int e = tid + u * 512;
            float4 v = xg[e];
            int tok = e / 24, c4 = (e % 24) * 4;
            u32 h0, l0, h1, l1;
            bsplit2(v.x, v.y, h0, l0);
            bsplit2(v.z, v.w, h1, l1);
            *reinterpret_cast<uint2*>(smc + XH_B + tok * 208 + c4 * 2) = make_uint2(h0, h1);
            *reinterpret_cast<uint2*>(smc + XL_B + tok * 208 + c4 * 2) = make_uint2(l0, l1);
        }
    }
    __syncthreads();

    // ---- A fragments (x rows) in registers, reused across all 9 chunks ----
    u32 xah[6][4], xal[6][4];
    #pragma unroll
    for (int ks = 0; ks < 6; ++ks) {
        ldmx4(xah[ks], a_h + ks * 32);
        ldmx4(xal[ks], a_l + ks * 32);
    }

    // ================= phase 1: QKV GEMM, 9 chunks of N=32, bf16x3 =================
    #pragma unroll 1
    for (int c = 0; c < 9; ++c) {
        if (c) __syncthreads();          // prev chunk's B ldmatrix reads done
        #pragma unroll
        for (int u = 0; u < 3; ++u) {    // STS staged W chunk from regs
            u32 hi, lo; bsplit2(wv0[u], wv1[u], hi, lo);
            *reinterpret_cast<u32*>(smc + WH_B + se_n[u] * 208 + se_k2[u] * 4) = hi;
            *reinterpret_cast<u32*>(smc + WL_B + se_n[u] * 208 + se_k2[u] * 4) = lo;
        }
        __syncthreads();
        if (c < 8) {                     // prefetch next chunk (overlaps MMA)
            #pragma unroll
            for (int u = 0; u < 3; ++u) {
                wv0[u] = qkv_w[(size_t)(2 * se_k2[u]) * 288 + (c + 1) * 32 + se_n[u]];
                wv1[u] = qkv_w[(size_t)(2 * se_k2[u] + 1) * 288 + (c + 1) * 32 + se_n[u]];
            }
        }

        float d[2][4] = {{0.f,0.f,0.f,0.f},{0.f,0.f,0.f,0.f}};
        #pragma unroll
        for (int ks = 0; ks < 6; ++ks) {
            u32 bh[4], bl[4];
            ldmx4(bh, b_h + ks * 32);
            ldmx4(bl, b_l + ks * 32);
            mma16816(d[0], xah[ks], bh[0], bh[2]);
            mma16816(d[0], xah[ks], bl[0], bl[2]);
            mma16816(d[0], xal[ks], bh[0], bh[2]);
            mma16816(d[1], xah[ks], bh[1], bh[3]);
            mma16816(d[1], xah[ks], bl[1], bl[3]);
            mma16816(d[1], xal[ks], bh[1], bh[3]);
        }

        // epilogue: +bias (Q also *0.25), split-pack into QH/KH/VH [tok][ch pairs]
        const int p = c / 3;
        const int base_h = (p == 0) ? QH_B : (p == 1) ? KH_B : VH_B;
        const int row0 = m * 16 + (lane >> 2);
        const int win = row0 >> 6, tk = row0 & 63;
        char* outh = smc + base_h + win * WINB + tk * 208;
        char* outl = outh + HLOFF;
        #pragma unroll
        for (int nt = 0; nt < 2; ++nt) {
            int g = c * 32 + nh * 16 + nt * 8 + 2 * (lane & 3);
            int ch = g % 96;
            float bb0 = qkv_b[g], bb1 = qkv_b[g + 1];
            float v00 = d[nt][0] + bb0, v01 = d[nt][1] + bb1;
            float v10 = d[nt][2] + bb0, v11 = d[nt][3] + bb1;
            if (p == 0) { v00 *= 0.25f; v01 *= 0.25f; v10 *= 0.25f; v11 *= 0.25f; }
            u32 hh, ll;
            bsplit2(v00, v01, hh, ll);
            *reinterpret_cast<u32*>(outh + (ch >> 1) * 4) = hh;
            *reinterpret_cast<u32*>(outl + (ch >> 1) * 4) = ll;
            bsplit2(v10, v11, hh, ll);
            *reinterpret_cast<u32*>(outh + 8 * 208 + (ch >> 1) * 4) = hh;
            *reinterpret_cast<u32*>(outl + 8 * 208 + (ch >> 1) * 4) = ll;
        }
    }
    __syncthreads();

    // ================= phase 2: attention, all-MMA, softmax in registers ==========
    {
        const int win  = wid >> 3;            // window 0/1
        const int hsub = (wid >> 2) & 1;      // head parity
        const int mt   = wid & 3;             // 16-row q tile
        const int r    = mt * 16 + (lane >> 2);
        const float* cw = cmb + (size_t)((2 * blockIdx.x + win) & (NW - 1)) * (HEADS * 4096);
        const u32 qbase = sb + QH_B + win * WINB + (u32)(mt * 16 + lrow) * 208 + lkoff;
        const u32 kbase = sb + KH_B + win * WINB + (u32)lrow * 208 + lkoff;
        const u32 vbase = sb + VH_B + win * WINB + (u32)lrow * 208 + lkoff;
        char* ooh = smc + XH_B + (win * 64 + mt * 16 + (lane >> 2)) * 208;
        char* ool = ooh + HLOFF;

        #pragma unroll 1
        for (int hi2 = 0; hi2 < 3; ++hi2) {
            const int h = 2 * hi2 + hsub;
            const u32 chb = h * 32;

            u32 qh4[4], ql4[4];
            ldmx4(qh4, qbase + chb);
            ldmx4(ql4, qbase + HLOFF + chb);

            float d[8][4];
            const float* cm = cw + h * 4096 + 2 * (lane & 3);
            #pragma unroll
            for (int j = 0; j < 8; ++j) {
                float2 c0 = *reinterpret_cast<const float2*>(&cm[r * 64 + 8 * j]);
                float2 c1 = *reinterpret_cast<const float2*>(&cm[(r + 8) * 64 + 8 * j]);
                d[j][0] = c0.x; d[j][1] = c0.y; d[j][2] = c1.x; d[j][3] = c1.y;
            }
            #pragma unroll
            for (int t = 0; t < 4; ++t) {
                u32 kh4[4], kl4[4];
                ldmx4(kh4, kbase + t * (16 * 208) + chb);
                ldmx4(kl4, kbase + HLOFF + t * (16 * 208) + chb);
                mma16816(d[2 * t],     qh4, kh4[0], kh4[2]);
                mma16816(d[2 * t],     qh4, kl4[0], kl4[2]);
                mma16816(d[2 * t],     ql4, kh4[0], kh4[2]);
                mma16816(d[2 * t + 1], qh4, kh4[1], kh4[3]);
                mma16816(d[2 * t + 1], qh4, kl4[1], kl4[3]);
                mma16816(d[2 * t + 1], ql4, kh4[1], kh4[3]);
            }

            float mx0 = -1e30f, mx1 = -1e30f;
            #pragma unroll
            for (int j = 0; j < 8; ++j) {
                mx0 = fmaxf(mx0, fmaxf(d[j][0], d[j][1]));
                mx1 = fmaxf(mx1, fmaxf(d[j][2], d[j][3]));
            }
            mx0 = fmaxf(mx0, __shfl_xor_sync(0xffffffffu, mx0, 1, 4));
            mx0 = fmaxf(mx0, __shfl_xor_sync(0xffffffffu, mx0, 2, 4));
            mx1 = fmaxf(mx1, __shfl_xor_sync(0xffffffffu, mx1, 1, 4));
            mx1 = fmaxf(mx1, __shfl_xor_sync(0xffffffffu, mx1, 2, 4));
            float s0 = 0.f, s1 = 0.f;
            #pragma unroll
            for (int j = 0; j < 8; ++j) {
                d[j][0] = __expf(d[j][0] - mx0); d[j][1] = __expf(d[j][1] - mx0);
                d[j][2] = __expf(d[j][2] - mx1); d[j][3] = __expf(d[j][3] - mx1);
                s0 += d[j][0] + d[j][1];
                s1 += d[j][2] + d[j][3];
            }
            s0 += __shfl_xor_sync(0xffffffffu, s0, 1, 4);
            s0 += __shfl_xor_sync(0xffffffffu, s0, 2, 4);
            s1 += __shfl_xor_sync(0xffffffffu, s1, 1, 4);
            s1 += __shfl_xor_sync(0xffffffffu, s1, 2, 4);
            const float inv0 = 1.0f / s0, inv1 = 1.0f / s1;

            float o0[4] = {0.f,0.f,0.f,0.f}, o1[4] = {0.f,0.f,0.f,0.f};
            #pragma unroll
            for (int ks = 0; ks < 4; ++ks) {
                u32 pah[4], pal[4];
                bsplit2(d[2*ks][0]   * inv0, d[2*ks][1]   * inv0, pah[0], pal[0]);
                bsplit2(d[2*ks][2]   * inv1, d[2*ks][3]   * inv1, pah[1], pal[1]);
                bsplit2(d[2*ks+1][0] * inv0, d[2*ks+1][1] * inv0, pah[2], pal[2]);
                bsplit2(d[2*ks+1][2] * inv1, d[2*ks+1][3] * inv1, pah[3], pal[3]);
                u32 vh4[4], vl4[4];
                ldmx4t(vh4, vbase + ks * (16 * 208) + chb);
                ldmx4t(vl4, vbase + HLOFF + ks * (16 * 208) + chb);
                mma16816(o0, pah, vh4[0], vh4[1]);
                mma16816(o0, pah, vl4[0], vl4[1]);
                mma16816(o0, pal, vh4[0], vh4[1]);
                mma16816(o1, pah, vh4[2], vh4[3]);
                mma16816(o1, pah, vl4[2], vl4[3]);
                mma16816(o1, pal, vh4[2], vh4[3]);
            }

            {
                int ch0 = h * 16 + 2 * (lane & 3);
                u32 hh, ll;
                bsplit2(o0[0], o0[1], hh, ll);
                *reinterpret_cast<u32*>(ooh + (ch0 >> 1) * 4) = hh;
                *reinterpret_cast<u32*>(ool + (ch0 >> 1) * 4) = ll;
                bsplit2(o0[2], o0[3], hh, ll);
                *reinterpret_cast<u32*>(ooh + 8 * 208 + (ch0 >> 1) * 4) = hh;
                *reinterpret_cast<u32*>(ool + 8 * 208 + (ch0 >> 1) * 4) = ll;
                int ch1 = ch0 + 8;
                bsplit2(o1[0], o1[1], hh, ll);
                *reinterpret_cast<u32*>(ooh + (ch1 >> 1) * 4) = hh;
                *reinterpret_cast<u32*>(ool + (ch1 >> 1) * 4) = ll;
                bsplit2(o1[2], o1[3], hh, ll);
                *reinterpret_cast<u32*>(ooh + 8 * 208 + (ch1 >> 1) * 4) = hh;
                *reinterpret_cast<u32*>(ool + 8 * 208 + (ch1 >> 1) * 4) = ll;
            }
        }
    }

    // ---- prefetch proj_w chunk 0 ----
    float pw0[3], pw1[3];
    #pragma unroll
    for (int u = 0; u < 3; ++u) {
        pw0[u] = proj_w[(size_t)(2 * se_k2[u]) * 96 + se_n[u]];
        pw1[u] = proj_w[(size_t)(2 * se_k2[u] + 1) * 96 + se_n[u]];
    }
    __syncthreads();

    // ---- A fragments (o rows) in registers, reused across 3 proj chunks ----
    u32 oah[6][4], oal[6][4];
    #pragma unroll
    for (int ks = 0; ks < 6; ++ks) {
        ldmx4(oah[ks], a_h + ks * 32);
        ldmx4(oal[ks], a_l + ks * 32);
    }

    // ================= phase 3: proj GEMM, 3 chunks of N=32, bf16x3 =================
    #pragma unroll 1
    for (int pc = 0; pc < 3; ++pc) {
        if (pc) __syncthreads();
        #pragma unroll
        for (int u = 0; u < 3; ++u) {
            u32 hi, lo; bsplit2(pw0[u], pw1[u], hi, lo);
            *reinterpret_cast<u32*>(smc + WH_B + se_n[u] * 208 + se_k2[u] * 4) = hi;
            *reinterpret_cast<u32*>(smc + WL_B + se_n[u] * 208 + se_k2[u] * 4) = lo;
        }
        __syncthreads();
        if (pc < 2) {
            #pragma unroll
            for (int u = 0; u < 3; ++u) {
                pw0[u] = proj_w[(size_t)(2 * se_k2[u]) * 96 + (pc + 1) * 32 + se_n[u]];
                pw1[u] = proj_w[(size_t)(2 * se_k2[u] + 1) * 96 + (pc + 1) * 32 + se_n[u]];
            }
        }

        float d[2][4] = {{0.f,0.f,0.f,0.f},{0.f,0.f,0.f,0.f}};
        #pragma unroll
        for (int ks = 0; ks < 6; ++ks) {
            u32 bh[4], bl[4];
            ldmx4(bh, b_h + ks * 32);
            ldmx4(bl, b_l + ks * 32);
            mma16816(d[0], oah[ks], bh[0], bh[2]);
            mma16816(d[0], oah[ks], bl[0], bl[2]);
            mma16816(d[0], oal[ks], bh[0], bh[2]);
            mma16816(d[1], oah[ks], bh[1], bh[3]);
            mma16816(d[1], oah[ks], bl[1], bl[3]);
            mma16816(d[1], oal[ks], bh[1], bh[3]);
        }

        float* og = out + (size_t)blockIdx.x * 128 * 96;
        const int row0 = m * 16 + (lane >> 2);
        #pragma unroll
        for (int nt = 0; nt < 2; ++nt) {
            int g = pc * 32 + nh * 16 + nt * 8 + 2 * (lane & 3);
            float b0 = proj_b[g], b1 = proj_b[g + 1];
            float2 v0 = make_float2(d[nt][0] + b0, d[nt][1] + b1);
            float2 v1 = make_float2(d[nt][2] + b0, d[nt][3] + b1);
            *reinterpret_cast<float2*>(og + (size_t)row0 * 96 + g)       = v0;
            *reinterpret_cast<float2*>(og + (size_t)(row0 + 8) * 96 + g) = v1;
        }
    }
}

extern "C" void kernel_launch(void* const* d_in, const int* in_sizes, int n_in,
                              void* d_out, int out_size)
{
    const float* x      = (const float*)d_in[0];
    const float* mask   = (const float*)d_in[1];
    const float* qkv_w  = (const float*)d_in[2];
    const float* qkv_b  = (const float*)d_in[3];
    const float* proj_w = (const float*)d_in[4];
    const float* proj_b = (const float*)d_in[5];
    const float* rpb    = (const float*)d_in[6];
    const int*   ridx   = (const int*)d_in[7];
    float* out = (float*)d_out;

    const int n_windows = in_sizes[0] / (NTOK * DIM);   // 8192

    cudaFuncSetAttribute(win_attn_kernel,
                         cudaFuncAttributeMaxDynamicSharedMemorySize, SMEM_BYTES);

    const int total = NW * HEADS * NTOK * NTOK;
    prep_kernel<<<(total + 255) / 256, 256>>>(rpb, ridx, mask);
    win_attn_kernel<<<n_windows / 2, 512, SMEM_BYTES>>>(
        x, qkv_w, qkv_b, proj_w, proj_b, out);
}